// round 14
// baseline (speedup 1.0000x reference)
#include <cuda_runtime.h>
#include <cuda_fp16.h>
#include <cstdint>

#define Nn 16
#define Cc 64
#define Hh 128
#define Ww 128

// gemm CTA: 2 h-rows x 64 w-positions (M = 128). smem = Xp only:
// 144 rows x 128B (block b at row 72b, rows 68..71 of each block unused)
#define SMEM_BYTES (144 * 128)
#define NTHR 256
#define NSLICE 4

#define SWZ(o) ((uint32_t)(o) ^ ((((uint32_t)(o)) >> 3) & 0x70))

// B fragments (fp16) in mma.sync per-lane order:
// gBfrag[tap(5)][kc(4)][nt8(8)][lane(32)] = {hi0, hi1, lo0, lo1}
__device__ __align__(16) uint4 g_Bfrag[5 * 4 * 8 * 32];

// t3 scratch: [n][co][h][w] f32 (same layout as out)
__device__ float g_t3[(size_t)Nn * Cc * Hh * Ww];

// pre-transposed fp16 x: [n][h][wp(136)][ci(64)], wp = w+2, pre-swizzled rows
__device__ __align__(16) __half g_xh[(size_t)Nn * Hh * 136 * 64];

// ---------------- helpers ----------------
__device__ __forceinline__ uint32_t smem_u32(const void* p) {
    uint32_t a;
    asm("{ .reg .u64 t; cvta.to.shared.u64 t, %1; cvt.u32.u64 %0, t; }" : "=r"(a) : "l"(p));
    return a;
}
__device__ __forceinline__ void ldx4(uint32_t* r, uint32_t addr) {
    asm volatile("ldmatrix.sync.aligned.m8n8.x4.shared.b16 {%0,%1,%2,%3}, [%4];"
                 : "=r"(r[0]), "=r"(r[1]), "=r"(r[2]), "=r"(r[3]) : "r"(addr));
}
__device__ __forceinline__ void mma_f16(float* d, const uint32_t* a, uint32_t b0, uint32_t b1) {
    asm volatile(
        "mma.sync.aligned.m16n8k16.row.col.f32.f16.f16.f32 "
        "{%0,%1,%2,%3}, {%4,%5,%6,%7}, {%8,%9}, {%0,%1,%2,%3};"
        : "+f"(d[0]), "+f"(d[1]), "+f"(d[2]), "+f"(d[3])
        : "r"(a[0]), "r"(a[1]), "r"(a[2]), "r"(a[3]), "r"(b0), "r"(b1));
}
__device__ __forceinline__ uint32_t pack_h2(float lo, float hi_) {
    __half2 p;
    p.x = __float2half(lo);
    p.y = __float2half(hi_);
    return *(uint32_t*)&p;
}

// ---------------- pre-kernel 1: B fragment table (fp16 hi/lo) ----------------
__global__ void convert_w_kernel(const float* __restrict__ w3) {
    int idx = blockIdx.x * 256 + threadIdx.x;
    if (idx >= 5 * 4 * 8 * 32) return;
    int lane = idx & 31;
    int nt8  = (idx >> 5) & 7;
    int kc   = (idx >> 8) & 3;
    int tap  = idx >> 10;

    int co  = nt8 * 8 + (lane >> 2);
    int ci0 = kc * 16 + (lane & 3) * 2;

    float v[4], hi[4], lo[4];
    #pragma unroll
    for (int q = 0; q < 4; q++) {
        int ci = ci0 + (q & 1) + (q >> 1) * 8;
        v[q] = w3[((size_t)co * Cc + ci) * 5 + tap];
        __half hb = __float2half(v[q]);
        hi[q] = __half2float(hb);
        lo[q] = v[q] - hi[q];
    }
    uint4 frag;
    frag.x = pack_h2(hi[0], hi[1]);
    frag.y = pack_h2(hi[2], hi[3]);
    frag.z = pack_h2(lo[0], lo[1]);
    frag.w = pack_h2(lo[2], lo[3]);
    g_Bfrag[idx] = frag;
}

// ---------------- pre-kernel 2: transpose+convert x -> g_xh ----------------
__global__ __launch_bounds__(256)
void xcvt_kernel(const float* __restrict__ x)
{
    __shared__ float tile[64][129];
    const int nh  = blockIdx.x;
    const int h   = nh & (Hh - 1);
    const int n   = nh >> 7;
    const int tid = threadIdx.x;

    for (int i = tid; i < 64 * 32; i += 256) {
        int f = i & 31, c = i >> 5;
        float4 v = *(const float4*)(x + (((size_t)n * Cc + c) * Hh + h) * Ww + 4 * f);
        tile[c][4 * f + 0] = v.x;
        tile[c][4 * f + 1] = v.y;
        tile[c][4 * f + 2] = v.z;
        tile[c][4 * f + 3] = v.w;
    }
    __syncthreads();

    uint32_t* gh = (uint32_t*)g_xh;
    const size_t rowbase = (size_t)nh * 136;
    for (int i = tid; i < 136 * 32; i += 256) {
        int ci2 = i & 31, wp = i >> 5;
        int w = wp - 2;
        uint32_t val = 0;
        if ((unsigned)w < (unsigned)Ww)
            val = pack_h2(tile[ci2 * 2][w], tile[ci2 * 2 + 1][w]);
        uint32_t boff = ((uint32_t)(ci2 * 4)) ^ ((uint32_t)(wp & 7) << 4);  // pre-swizzle
        gh[(rowbase + wp) * 32 + (boff >> 2)] = val;
    }
}

// ---------------- gemm slice: h in [slice*32, slice*32+32) -> g_t3 ----------------
__global__ __launch_bounds__(NTHR, 2)
void gemm_kernel(int slice)
{
    extern __shared__ char smem[];
    const uint32_t sbase = smem_u32(smem);

    const int tid  = threadIdx.x;
    const int wid  = tid >> 5;
    const int lane = tid & 31;
    const int wblk = blockIdx.x & 1;
    const int h0   = (slice * 16 + ((blockIdx.x >> 1) & 15)) * 2;
    const int n    = blockIdx.x >> 5;
    const int w0   = wblk * 64;

    // ---- stage Xp: verbatim copy of pre-swizzled fp16 rows ----
    {
        const uint4* src0 = (const uint4*)g_xh + ((size_t)(n * Hh + h0)     * 136 + w0) * 8;
        const uint4* src1 = (const uint4*)g_xh + ((size_t)(n * Hh + h0 + 1) * 136 + w0) * 8;
        uint4* d = (uint4*)smem;
        for (int i = tid; i < 1088; i += NTHR) {       // 2 * 68 rows * 8 uint4
            int b = (i >= 544);
            int j = i - 544 * b;
            uint4 v = b ? src1[j] : src0[j];
            d[b * 576 + j] = v;                         // 72 rows * 8 = 576
        }
    }
    __syncthreads();

    // ---- warp tiling: 4 (m32) x 2 (n32) ----
    const int warp_m = wid & 3;
    const int warp_n = wid >> 2;
    const int arow_base = (warp_m < 2) ? (32 * warp_m) : (72 + 32 * (warp_m - 2));
    const int mlg_base  = 32 * warp_m;

    const int gid = lane >> 2;
    const int tig = lane & 3;
    const int arow   = (lane & 7) + ((lane >> 3) & 1) * 8;
    const int acol16 = (lane >> 4) * 16;

    const uint4* bt = g_Bfrag + (size_t)(warp_n * 4) * 32 + lane;

    float acc[2][4][4];
    #pragma unroll
    for (int mt = 0; mt < 2; mt++)
        #pragma unroll
        for (int nt = 0; nt < 4; nt++)
            #pragma unroll
            for (int r = 0; r < 4; r++) acc[mt][nt][r] = 0.f;

    uint32_t aH[2][2][4];
    uint4 bf[2][4];

    #define LOAD_STAGE(s, buf) do {                                                \
        const int _tap = (s) >> 2, _kc = (s) & 3;                                  \
        _Pragma("unroll")                                                          \
        for (int mt = 0; mt < 2; mt++) {                                           \
            uint32_t rel = (uint32_t)((arow_base + 16 * mt + _tap + arow) * 128    \
                                      + _kc * 32 + acol16);                        \
            ldx4(aH[buf][mt], sbase + SWZ(rel));                                   \
        }                                                                          \
        _Pragma("unroll")                                                          \
        for (int nt = 0; nt < 4; nt++)                                             \
            bf[buf][nt] = __ldg(bt + (size_t)(_tap * 4 + _kc) * 256 + nt * 32);    \
    } while (0)

    #define MMA_STAGE(buf) do {                                                    \
        _Pragma("unroll")                                                          \
        for (int mt = 0; mt < 2; mt++)                                             \
            _Pragma("unroll")                                                      \
            for (int nt = 0; nt < 4; nt++)                                         \
                mma_f16(acc[mt][nt], aH[buf][mt], bf[buf][nt].x, bf[buf][nt].y);   \
        _Pragma("unroll")                                                          \
        for (int mt = 0; mt < 2; mt++)                                             \
            _Pragma("unroll")                                                      \
            for (int nt = 0; nt < 4; nt++)                                         \
                mma_f16(acc[mt][nt], aH[buf][mt], bf[buf][nt].z, bf[buf][nt].w);   \
    } while (0)

    LOAD_STAGE(0, 0);
    #pragma unroll
    for (int s = 0; s < 20; s++) {
        if (s + 1 < 20) {
            if ((s & 1) == 0) LOAD_STAGE(s + 1, 1);
            else              LOAD_STAGE(s + 1, 0);
        }
        if ((s & 1) == 0) MMA_STAGE(0);
        else              MMA_STAGE(1);
    }
    #undef LOAD_STAGE
    #undef MMA_STAGE

    // ---- store t3 to scratch ----
    #pragma unroll
    for (int nt = 0; nt < 4; nt++) {
        #pragma unroll
        for (int j = 0; j < 2; j++) {
            const int co = 32 * warp_n + 8 * nt + 2 * tig + j;
            #pragma unroll
            for (int mt = 0; mt < 2; mt++) {
                #pragma unroll
                for (int p = 0; p < 2; p++) {
                    const int mlg = mlg_base + 16 * mt + gid + 8 * p;
                    const int rr  = mlg >> 6;
                    const int wl  = mlg & 63;
                    g_t3[(((size_t)n * Cc + co) * Hh + (h0 + rr)) * Ww + (w0 + wl)]
                        = acc[mt][nt][2 * p + j];
                }
            }
        }
    }
}

// ---------------- epilogue slice: t7 * t3 -> out for h in slice ----------------
__global__ __launch_bounds__(256)
void epilogue_kernel(const float* __restrict__ x,
                     const float* __restrict__ w7,
                     float* __restrict__ out,
                     int slice)
{
    const int rowid = blockIdx.x * 8 + (threadIdx.x >> 5);
    const int lane  = threadIdx.x & 31;
    const int h  = slice * 32 + (rowid & 31);
    const int co = (rowid >> 5) & (Cc - 1);
    const int n  = rowid >> 11;
    const int w  = lane * 4;

    const float* xc = x + ((size_t)n * Cc + co) * Hh * Ww;
    const size_t oidx = (((size_t)n * Cc + co) * Hh + h) * Ww + w;

    float win[3][12];
    #pragma unroll
    for (int i = 0; i < 3; i++) {
        const int hh = h + i - 1;
        if ((unsigned)hh < (unsigned)Hh) {
            const float* xr = xc + (size_t)hh * Ww;
            #pragma unroll
            for (int q = 0; q < 3; q++) {
                const int ww = w - 4 + 4 * q;
                float4 v = make_float4(0.f, 0.f, 0.f, 0.f);
                if ((unsigned)ww < (unsigned)Ww)
                    v = *(const float4*)(xr + ww);
                win[i][4 * q + 0] = v.x;
                win[i][4 * q + 1] = v.y;
                win[i][4 * q + 2] = v.z;
                win[i][4 * q + 3] = v.w;
            }
        } else {
            #pragma unroll
            for (int j = 0; j < 12; j++) win[i][j] = 0.f;
        }
    }

    const float4 t3v = *(const float4*)(g_t3 + oidx);
    float wk[9];
    #pragma unroll
    for (int q = 0; q < 9; q++) wk[q] = __ldg(w7 + co * 9 + q);

    float res[4];
    #pragma unroll
    for (int k = 0; k < 4; k++) {
        float t7 = 0.f;
        if (k > 0 || w != 0) {
            #pragma unroll
            for (int i = 0; i < 3; i++) {
                const float t1 = win[1][k + 2 * i + 2];
                #pragma unroll
                for (int jj = 0; jj < 3; jj++) {
                    const float t5 = win[i][k + 2 * jj + 1];
                    t7 = fmaf(wk[3 * jj + i], fmaxf(t1, t5), t7);
                }
            }
        } else {
            // w+k == 0: roll wraps -> wr = 127; t5 = x[co, h+i-1, 125+2jj] (129 -> 0)
            #pragma unroll
            for (int i = 0; i < 3; i++) {
                const int hh = h + i - 1;
                const float t1 = win[1][2 * i + 2];
                #pragma unroll
                for (int jj = 0; jj < 3; jj++) {
                    const int ww = 125 + 2 * jj;
                    float t5 = 0.f;
                    if ((unsigned)hh < (unsigned)Hh && ww < Ww)
                        t5 = xc[(size_t)hh * Ww + ww];
                    t7 = fmaf(wk[3 * jj + i], fmaxf(t1, t5), t7);
                }
            }
        }
        res[k] = t7;
    }
    float4 o;
    o.x = res[0] * t3v.x;
    o.y = res[1] * t3v.y;
    o.z = res[2] * t3v.z;
    o.w = res[3] * t3v.w;
    *(float4*)(out + oidx) = o;
}

// fork-join resources (created on the first, uncaptured, correctness call)
static cudaStream_t s_side = nullptr;
static cudaEvent_t  s_evG[NSLICE];
static cudaEvent_t  s_evJoin = nullptr;

extern "C" void kernel_launch(void* const* d_in, const int* in_sizes, int n_in,
                              void* d_out, int out_size)
{
    const float* x  = (const float*)d_in[0];
    const float* w3 = (const float*)d_in[1];
    const float* w7 = (const float*)d_in[2];
    float* out = (float*)d_out;

    if (s_side == nullptr) {
        cudaStreamCreateWithFlags(&s_side, cudaStreamNonBlocking);
        for (int k = 0; k < NSLICE; k++)
            cudaEventCreateWithFlags(&s_evG[k], cudaEventDisableTiming);
        cudaEventCreateWithFlags(&s_evJoin, cudaEventDisableTiming);
        cudaFuncSetAttribute(gemm_kernel,
                             cudaFuncAttributeMaxDynamicSharedMemorySize, SMEM_BYTES);
    }

    convert_w_kernel<<<20, 256>>>(w3);
    xcvt_kernel<<<Nn * Hh, 256>>>(x);

    for (int k = 0; k < NSLICE; k++) {
        gemm_kernel<<<Nn * 16 * 2, NTHR, SMEM_BYTES>>>(k);
        cudaEventRecord(s_evG[k], 0);
        cudaStreamWaitEvent(s_side, s_evG[k], 0);
        epilogue_kernel<<<Nn * Cc * 32 / 8, 256, 0, s_side>>>(x, w7, out, k);
    }
    cudaEventRecord(s_evJoin, s_side);
    cudaStreamWaitEvent(0, s_evJoin, 0);
}

// round 15
// speedup vs baseline: 1.1832x; 1.1832x over previous
#include <cuda_runtime.h>
#include <cuda_fp16.h>
#include <cstdint>

#define Nn 16
#define Cc 64
#define Hh 128
#define Ww 128

// gemm CTA: 2 h-rows x 64 w-positions (M = 128). smem = Xp only:
// 144 rows x 128B (block b at row 72b, rows 68..71 of each block unused)
#define SMEM_BYTES (144 * 128)
#define NTHR 256

#define SWZ(o) ((uint32_t)(o) ^ ((((uint32_t)(o)) >> 3) & 0x70))

// B fragments (fp16) in mma.sync per-lane order:
// gBfrag[tap(5)][kc(4)][nt8(8)][lane(32)] = {hi0, hi1, lo0, lo1}
__device__ __align__(16) uint4 g_Bfrag[5 * 4 * 8 * 32];

// t3 scratch (fp16): [n][co][h][w], same index layout as out
__device__ __align__(16) __half g_t3h[(size_t)Nn * Cc * Hh * Ww];

// pre-transposed fp16 x: [n][h][wp(136)][ci(64)], wp = w+2, pre-swizzled rows
__device__ __align__(16) __half g_xh[(size_t)Nn * Hh * 136 * 64];

// ---------------- helpers ----------------
__device__ __forceinline__ uint32_t smem_u32(const void* p) {
    uint32_t a;
    asm("{ .reg .u64 t; cvta.to.shared.u64 t, %1; cvt.u32.u64 %0, t; }" : "=r"(a) : "l"(p));
    return a;
}
__device__ __forceinline__ void ldx4(uint32_t* r, uint32_t addr) {
    asm volatile("ldmatrix.sync.aligned.m8n8.x4.shared.b16 {%0,%1,%2,%3}, [%4];"
                 : "=r"(r[0]), "=r"(r[1]), "=r"(r[2]), "=r"(r[3]) : "r"(addr));
}
__device__ __forceinline__ void mma_f16(float* d, const uint32_t* a, uint32_t b0, uint32_t b1) {
    asm volatile(
        "mma.sync.aligned.m16n8k16.row.col.f32.f16.f16.f32 "
        "{%0,%1,%2,%3}, {%4,%5,%6,%7}, {%8,%9}, {%0,%1,%2,%3};"
        : "+f"(d[0]), "+f"(d[1]), "+f"(d[2]), "+f"(d[3])
        : "r"(a[0]), "r"(a[1]), "r"(a[2]), "r"(a[3]), "r"(b0), "r"(b1));
}
__device__ __forceinline__ uint32_t pack_h2(float lo, float hi_) {
    __half2 p;
    p.x = __float2half(lo);
    p.y = __float2half(hi_);
    return *(uint32_t*)&p;
}

// ---------------- pre-kernel 1: B fragment table (fp16 hi/lo) ----------------
__global__ void convert_w_kernel(const float* __restrict__ w3) {
    int idx = blockIdx.x * 256 + threadIdx.x;
    if (idx >= 5 * 4 * 8 * 32) return;
    int lane = idx & 31;
    int nt8  = (idx >> 5) & 7;
    int kc   = (idx >> 8) & 3;
    int tap  = idx >> 10;

    int co  = nt8 * 8 + (lane >> 2);
    int ci0 = kc * 16 + (lane & 3) * 2;

    float v[4], hi[4], lo[4];
    #pragma unroll
    for (int q = 0; q < 4; q++) {
        int ci = ci0 + (q & 1) + (q >> 1) * 8;
        v[q] = w3[((size_t)co * Cc + ci) * 5 + tap];
        __half hb = __float2half(v[q]);
        hi[q] = __half2float(hb);
        lo[q] = v[q] - hi[q];
    }
    uint4 frag;
    frag.x = pack_h2(hi[0], hi[1]);
    frag.y = pack_h2(hi[2], hi[3]);
    frag.z = pack_h2(lo[0], lo[1]);
    frag.w = pack_h2(lo[2], lo[3]);
    g_Bfrag[idx] = frag;
}

// ---------------- pre-kernel 2: transpose+convert x -> g_xh ----------------
__global__ __launch_bounds__(256)
void xcvt_kernel(const float* __restrict__ x)
{
    __shared__ float tile[64][129];
    const int nh  = blockIdx.x;
    const int h   = nh & (Hh - 1);
    const int n   = nh >> 7;
    const int tid = threadIdx.x;

    for (int i = tid; i < 64 * 32; i += 256) {
        int f = i & 31, c = i >> 5;
        float4 v = *(const float4*)(x + (((size_t)n * Cc + c) * Hh + h) * Ww + 4 * f);
        tile[c][4 * f + 0] = v.x;
        tile[c][4 * f + 1] = v.y;
        tile[c][4 * f + 2] = v.z;
        tile[c][4 * f + 3] = v.w;
    }
    __syncthreads();

    uint32_t* gh = (uint32_t*)g_xh;
    const size_t rowbase = (size_t)nh * 136;
    for (int i = tid; i < 136 * 32; i += 256) {
        int ci2 = i & 31, wp = i >> 5;
        int w = wp - 2;
        uint32_t val = 0;
        if ((unsigned)w < (unsigned)Ww)
            val = pack_h2(tile[ci2 * 2][w], tile[ci2 * 2 + 1][w]);
        uint32_t boff = ((uint32_t)(ci2 * 4)) ^ ((uint32_t)(wp & 7) << 4);  // pre-swizzle
        gh[(rowbase + wp) * 32 + (boff >> 2)] = val;
    }
}

// ---------------- main kernel: pure GEMM -> g_t3h ----------------
__global__ __launch_bounds__(NTHR, 2)
void gemm_kernel()
{
    extern __shared__ char smem[];
    const uint32_t sbase = smem_u32(smem);

    const int tid  = threadIdx.x;
    const int wid  = tid >> 5;
    const int lane = tid & 31;
    const int wblk = blockIdx.x & 1;
    const int h0   = ((blockIdx.x >> 1) & 63) * 2;
    const int n    = blockIdx.x >> 7;
    const int w0   = wblk * 64;

    // ---- stage Xp: verbatim copy of pre-swizzled fp16 rows ----
    {
        const uint4* src0 = (const uint4*)g_xh + ((size_t)(n * Hh + h0)     * 136 + w0) * 8;
        const uint4* src1 = (const uint4*)g_xh + ((size_t)(n * Hh + h0 + 1) * 136 + w0) * 8;
        uint4* d = (uint4*)smem;
        for (int i = tid; i < 1088; i += NTHR) {       // 2 * 68 rows * 8 uint4
            int b = (i >= 544);
            int j = i - 544 * b;
            uint4 v = b ? src1[j] : src0[j];
            d[b * 576 + j] = v;                         // 72 rows * 8 = 576
        }
    }
    __syncthreads();

    // ---- warp tiling: 4 (m32) x 2 (n32) ----
    const int warp_m = wid & 3;
    const int warp_n = wid >> 2;
    const int arow_base = (warp_m < 2) ? (32 * warp_m) : (72 + 32 * (warp_m - 2));
    const int mlg_base  = 32 * warp_m;

    const int gid = lane >> 2;
    const int tig = lane & 3;
    const int arow   = (lane & 7) + ((lane >> 3) & 1) * 8;
    const int acol16 = (lane >> 4) * 16;

    const uint4* bt = g_Bfrag + (size_t)(warp_n * 4) * 32 + lane;

    float acc[2][4][4];
    #pragma unroll
    for (int mt = 0; mt < 2; mt++)
        #pragma unroll
        for (int nt = 0; nt < 4; nt++)
            #pragma unroll
            for (int r = 0; r < 4; r++) acc[mt][nt][r] = 0.f;

    uint32_t aH[2][2][4];
    uint4 bf[2][4];

    #define LOAD_STAGE(s, buf) do {                                                \
        const int _tap = (s) >> 2, _kc = (s) & 3;                                  \
        _Pragma("unroll")                                                          \
        for (int mt = 0; mt < 2; mt++) {                                           \
            uint32_t rel = (uint32_t)((arow_base + 16 * mt + _tap + arow) * 128    \
                                      + _kc * 32 + acol16);                        \
            ldx4(aH[buf][mt], sbase + SWZ(rel));                                   \
        }                                                                          \
        _Pragma("unroll")                                                          \
        for (int nt = 0; nt < 4; nt++)                                             \
            bf[buf][nt] = __ldg(bt + (size_t)(_tap * 4 + _kc) * 256 + nt * 32);    \
    } while (0)

    #define MMA_STAGE(buf) do {                                                    \
        _Pragma("unroll")                                                          \
        for (int mt = 0; mt < 2; mt++)                                             \
            _Pragma("unroll")                                                      \
            for (int nt = 0; nt < 4; nt++)                                         \
                mma_f16(acc[mt][nt], aH[buf][mt], bf[buf][nt].x, bf[buf][nt].y);   \
        _Pragma("unroll")                                                          \
        for (int mt = 0; mt < 2; mt++)                                             \
            _Pragma("unroll")                                                      \
            for (int nt = 0; nt < 4; nt++)                                         \
                mma_f16(acc[mt][nt], aH[buf][mt], bf[buf][nt].z, bf[buf][nt].w);   \
    } while (0)

    LOAD_STAGE(0, 0);
    #pragma unroll
    for (int s = 0; s < 20; s++) {
        if (s + 1 < 20) {
            if ((s & 1) == 0) LOAD_STAGE(s + 1, 1);
            else              LOAD_STAGE(s + 1, 0);
        }
        if ((s & 1) == 0) MMA_STAGE(0);
        else              MMA_STAGE(1);
    }
    #undef LOAD_STAGE
    #undef MMA_STAGE

    // ---- store t3 (fp16) to scratch ----
    #pragma unroll
    for (int nt = 0; nt < 4; nt++) {
        #pragma unroll
        for (int j = 0; j < 2; j++) {
            const int co = 32 * warp_n + 8 * nt + 2 * tig + j;
            #pragma unroll
            for (int mt = 0; mt < 2; mt++) {
                #pragma unroll
                for (int p = 0; p < 2; p++) {
                    const int mlg = mlg_base + 16 * mt + gid + 8 * p;
                    const int rr  = mlg >> 6;
                    const int wl  = mlg & 63;
                    g_t3h[(((size_t)n * Cc + co) * Hh + (h0 + rr)) * Ww + (w0 + wl)]
                        = __float2half(acc[mt][nt][2 * p + j]);
                }
            }
        }
    }
}

// ---------------- epilogue: one CTA per (n, co, 32-h chunk), smem-staged x ----------------
__global__ __launch_bounds__(256)
void epilogue_kernel(const float* __restrict__ x,
                     const float* __restrict__ w7,
                     float* __restrict__ out)
{
    __shared__ float sx[34][136];        // rows h0-1..h0+32; p = col+4; pads zero
    const int blk = blockIdx.x;
    const int h0  = (blk & 3) * 32;
    const int co  = (blk >> 2) & (Cc - 1);
    const int n   = blk >> 8;
    const int tid = threadIdx.x;
    const int wid = tid >> 5;
    const int lane = tid & 31;

    const float* xc = x + ((size_t)n * Cc + co) * Hh * Ww;

    // stage: 34 rows x 34 float4
    for (int i = tid; i < 34 * 34; i += 256) {
        int s = i / 34, q = i - s * 34;
        int hh  = h0 - 1 + s;
        int col = 4 * q - 4;
        float4 v = make_float4(0.f, 0.f, 0.f, 0.f);
        if ((unsigned)hh < (unsigned)Hh && (unsigned)col < (unsigned)Ww)
            v = *(const float4*)(xc + (size_t)hh * Ww + col);
        *(float4*)(&sx[s][4 * q]) = v;
    }
    __syncthreads();

    float wk[9];
    #pragma unroll
    for (int q = 0; q < 9; q++) wk[q] = __ldg(w7 + co * 9 + q);

    const int w = lane * 4;

    #pragma unroll
    for (int r = 0; r < 4; r++) {
        const int hl = wid * 4 + r;                 // local h (0..31)
        const int h  = h0 + hl;

        // win[i][j] = x[co, h+i-1, w-4+j], j=0..11  (smem row hl+i, p = w+4q2)
        float win[3][12];
        #pragma unroll
        for (int i = 0; i < 3; i++) {
            #pragma unroll
            for (int q2 = 0; q2 < 3; q2++) {
                float4 v = *(const float4*)(&sx[hl + i][w + 4 * q2]);
                win[i][4 * q2 + 0] = v.x;
                win[i][4 * q2 + 1] = v.y;
                win[i][4 * q2 + 2] = v.z;
                win[i][4 * q2 + 3] = v.w;
            }
        }

        const size_t oidx = (((size_t)n * Cc + co) * Hh + h) * Ww + w;
        // t3 (fp16 x4 -> f32)
        const __half2* t3p = (const __half2*)(g_t3h + oidx);
        float2 t3a = __half22float2(t3p[0]);
        float2 t3b = __half22float2(t3p[1]);
        float t3f[4] = {t3a.x, t3a.y, t3b.x, t3b.y};

        float res[4];
        #pragma unroll
        for (int k = 0; k < 4; k++) {
            float t7 = 0.f;
            if (k > 0 || w != 0) {
                #pragma unroll
                for (int i = 0; i < 3; i++) {
                    const float t1 = win[1][k + 2 * i + 2];
                    #pragma unroll
                    for (int jj = 0; jj < 3; jj++) {
                        const float t5 = win[i][k + 2 * jj + 1];
                        t7 = fmaf(wk[3 * jj + i], fmaxf(t1, t5), t7);
                    }
                }
            } else {
                // w == 0: roll wraps -> wr = 127; t5 = x[co, h+i-1, 125+2jj] -> p = 129+2jj
                // (col 129 OOB -> pad zero)
                #pragma unroll
                for (int i = 0; i < 3; i++) {
                    const float t1 = win[1][2 * i + 2];
                    #pragma unroll
                    for (int jj = 0; jj < 3; jj++) {
                        const float t5 = sx[hl + i][129 + 2 * jj];
                        t7 = fmaf(wk[3 * jj + i], fmaxf(t1, t5), t7);
                    }
                }
            }
            res[k] = t7;
        }
        float4 o;
        o.x = res[0] * t3f[0];
        o.y = res[1] * t3f[1];
        o.z = res[2] * t3f[2];
        o.w = res[3] * t3f[3];
        *(float4*)(out + oidx) = o;
    }
}

extern "C" void kernel_launch(void* const* d_in, const int* in_sizes, int n_in,
                              void* d_out, int out_size)
{
    const float* x  = (const float*)d_in[0];
    const float* w3 = (const float*)d_in[1];
    const float* w7 = (const float*)d_in[2];
    float* out = (float*)d_out;

    convert_w_kernel<<<20, 256>>>(w3);
    xcvt_kernel<<<Nn * Hh, 256>>>(x);

    cudaFuncSetAttribute(gemm_kernel,
                         cudaFuncAttributeMaxDynamicSharedMemorySize, SMEM_BYTES);
    gemm_kernel<<<Nn * 64 * 2, NTHR, SMEM_BYTES>>>();

    epilogue_kernel<<<Nn * Cc * 4, 256>>>(x, w7, out);
}

// round 16
// speedup vs baseline: 1.1856x; 1.0020x over previous
#include <cuda_runtime.h>
#include <cuda_fp16.h>
#include <cstdint>

#define Nn 16
#define Cc 64
#define Hh 128
#define Ww 128

// gemm CTA: 2 h-rows x 64 w-positions (M = 128). smem = Xp only:
#define SMEM_BYTES (144 * 128)
#define NTHR 256

#define SWZ(o) ((uint32_t)(o) ^ ((((uint32_t)(o)) >> 3) & 0x70))

// B fragments (fp16) in mma.sync per-lane order
__device__ __align__(16) uint4 g_Bfrag[5 * 4 * 8 * 32];
// t3 scratch (fp16): [n][co][h][w]
__device__ __align__(16) __half g_t3h[(size_t)Nn * Cc * Hh * Ww];
// pre-transposed fp16 x: [n][h][wp(136)][ci(64)], pre-swizzled rows
__device__ __align__(16) __half g_xh[(size_t)Nn * Hh * 136 * 64];

// ---------------- helpers ----------------
__device__ __forceinline__ uint32_t smem_u32(const void* p) {
    uint32_t a;
    asm("{ .reg .u64 t; cvta.to.shared.u64 t, %1; cvt.u32.u64 %0, t; }" : "=r"(a) : "l"(p));
    return a;
}
__device__ __forceinline__ void ldx4(uint32_t* r, uint32_t addr) {
    asm volatile("ldmatrix.sync.aligned.m8n8.x4.shared.b16 {%0,%1,%2,%3}, [%4];"
                 : "=r"(r[0]), "=r"(r[1]), "=r"(r[2]), "=r"(r[3]) : "r"(addr));
}
__device__ __forceinline__ void mma_f16(float* d, const uint32_t* a, uint32_t b0, uint32_t b1) {
    asm volatile(
        "mma.sync.aligned.m16n8k16.row.col.f32.f16.f16.f32 "
        "{%0,%1,%2,%3}, {%4,%5,%6,%7}, {%8,%9}, {%0,%1,%2,%3};"
        : "+f"(d[0]), "+f"(d[1]), "+f"(d[2]), "+f"(d[3])
        : "r"(a[0]), "r"(a[1]), "r"(a[2]), "r"(a[3]), "r"(b0), "r"(b1));
}
__device__ __forceinline__ uint32_t pack_h2(float lo, float hi_) {
    __half2 p;
    p.x = __float2half(lo);
    p.y = __float2half(hi_);
    return *(uint32_t*)&p;
}

// ---------------- pre-kernel: xcvt (blocks 0..2047) + convert_w (blocks 2048..2067) ----------------
__global__ __launch_bounds__(256)
void prep_kernel(const float* __restrict__ x, const float* __restrict__ w3)
{
    if (blockIdx.x >= Nn * Hh) {
        // ---- B fragment table (fp16 hi/lo) ----
        int idx = (blockIdx.x - Nn * Hh) * 256 + threadIdx.x;
        if (idx >= 5 * 4 * 8 * 32) return;
        int lane = idx & 31;
        int nt8  = (idx >> 5) & 7;
        int kc   = (idx >> 8) & 3;
        int tap  = idx >> 10;

        int co  = nt8 * 8 + (lane >> 2);
        int ci0 = kc * 16 + (lane & 3) * 2;

        float v[4], hi[4], lo[4];
        #pragma unroll
        for (int q = 0; q < 4; q++) {
            int ci = ci0 + (q & 1) + (q >> 1) * 8;
            v[q] = w3[((size_t)co * Cc + ci) * 5 + tap];
            __half hb = __float2half(v[q]);
            hi[q] = __half2float(hb);
            lo[q] = v[q] - hi[q];
        }
        uint4 frag;
        frag.x = pack_h2(hi[0], hi[1]);
        frag.y = pack_h2(hi[2], hi[3]);
        frag.z = pack_h2(lo[0], lo[1]);
        frag.w = pack_h2(lo[2], lo[3]);
        g_Bfrag[idx] = frag;
        return;
    }

    // ---- transpose+convert x -> g_xh ----
    __shared__ float tile[64][129];
    const int nh  = blockIdx.x;
    const int h   = nh & (Hh - 1);
    const int n   = nh >> 7;
    const int tid = threadIdx.x;

    for (int i = tid; i < 64 * 32; i += 256) {
        int f = i & 31, c = i >> 5;
        float4 v = *(const float4*)(x + (((size_t)n * Cc + c) * Hh + h) * Ww + 4 * f);
        tile[c][4 * f + 0] = v.x;
        tile[c][4 * f + 1] = v.y;
        tile[c][4 * f + 2] = v.z;
        tile[c][4 * f + 3] = v.w;
    }
    __syncthreads();

    uint32_t* gh = (uint32_t*)g_xh;
    const size_t rowbase = (size_t)nh * 136;
    for (int i = tid; i < 136 * 32; i += 256) {
        int ci2 = i & 31, wp = i >> 5;
        int w = wp - 2;
        uint32_t val = 0;
        if ((unsigned)w < (unsigned)Ww)
            val = pack_h2(tile[ci2 * 2][w], tile[ci2 * 2 + 1][w]);
        uint32_t boff = ((uint32_t)(ci2 * 4)) ^ ((uint32_t)(wp & 7) << 4);
        gh[(rowbase + wp) * 32 + (boff >> 2)] = val;
    }
}

// ---------------- main kernel: pure GEMM -> g_t3h ----------------
__global__ __launch_bounds__(NTHR, 2)
void gemm_kernel()
{
    extern __shared__ char smem[];
    const uint32_t sbase = smem_u32(smem);

    const int tid  = threadIdx.x;
    const int wid  = tid >> 5;
    const int lane = tid & 31;
    const int wblk = blockIdx.x & 1;
    const int h0   = ((blockIdx.x >> 1) & 63) * 2;
    const int n    = blockIdx.x >> 7;
    const int w0   = wblk * 64;

    {
        const uint4* src0 = (const uint4*)g_xh + ((size_t)(n * Hh + h0)     * 136 + w0) * 8;
        const uint4* src1 = (const uint4*)g_xh + ((size_t)(n * Hh + h0 + 1) * 136 + w0) * 8;
        uint4* d = (uint4*)smem;
        for (int i = tid; i < 1088; i += NTHR) {
            int b = (i >= 544);
            int j = i - 544 * b;
            uint4 v = b ? src1[j] : src0[j];
            d[b * 576 + j] = v;
        }
    }
    __syncthreads();

    const int warp_m = wid & 3;
    const int warp_n = wid >> 2;
    const int arow_base = (warp_m < 2) ? (32 * warp_m) : (72 + 32 * (warp_m - 2));
    const int mlg_base  = 32 * warp_m;

    const int gid = lane >> 2;
    const int tig = lane & 3;
    const int arow   = (lane & 7) + ((lane >> 3) & 1) * 8;
    const int acol16 = (lane >> 4) * 16;

    const uint4* bt = g_Bfrag + (size_t)(warp_n * 4) * 32 + lane;

    float acc[2][4][4];
    #pragma unroll
    for (int mt = 0; mt < 2; mt++)
        #pragma unroll
        for (int nt = 0; nt < 4; nt++)
            #pragma unroll
            for (int r = 0; r < 4; r++) acc[mt][nt][r] = 0.f;

    uint32_t aH[2][2][4];
    uint4 bf[2][4];

    #define LOAD_STAGE(s, buf) do {                                                \
        const int _tap = (s) >> 2, _kc = (s) & 3;                                  \
        _Pragma("unroll")                                                          \
        for (int mt = 0; mt < 2; mt++) {                                           \
            uint32_t rel = (uint32_t)((arow_base + 16 * mt + _tap + arow) * 128    \
                                      + _kc * 32 + acol16);                        \
            ldx4(aH[buf][mt], sbase + SWZ(rel));                                   \
        }                                                                          \
        _Pragma("unroll")                                                          \
        for (int nt = 0; nt < 4; nt++)                                             \
            bf[buf][nt] = __ldg(bt + (size_t)(_tap * 4 + _kc) * 256 + nt * 32);    \
    } while (0)

    #define MMA_STAGE(buf) do {                                                    \
        _Pragma("unroll")                                                          \
        for (int mt = 0; mt < 2; mt++)                                             \
            _Pragma("unroll")                                                      \
            for (int nt = 0; nt < 4; nt++)                                         \
                mma_f16(acc[mt][nt], aH[buf][mt], bf[buf][nt].x, bf[buf][nt].y);   \
        _Pragma("unroll")                                                          \
        for (int mt = 0; mt < 2; mt++)                                             \
            _Pragma("unroll")                                                      \
            for (int nt = 0; nt < 4; nt++)                                         \
                mma_f16(acc[mt][nt], aH[buf][mt], bf[buf][nt].z, bf[buf][nt].w);   \
    } while (0)

    LOAD_STAGE(0, 0);
    #pragma unroll
    for (int s = 0; s < 20; s++) {
        if (s + 1 < 20) {
            if ((s & 1) == 0) LOAD_STAGE(s + 1, 1);
            else              LOAD_STAGE(s + 1, 0);
        }
        if ((s & 1) == 0) MMA_STAGE(0);
        else              MMA_STAGE(1);
    }
    #undef LOAD_STAGE
    #undef MMA_STAGE

    #pragma unroll
    for (int nt = 0; nt < 4; nt++) {
        #pragma unroll
        for (int j = 0; j < 2; j++) {
            const int co = 32 * warp_n + 8 * nt + 2 * tig + j;
            #pragma unroll
            for (int mt = 0; mt < 2; mt++) {
                #pragma unroll
                for (int p = 0; p < 2; p++) {
                    const int mlg = mlg_base + 16 * mt + gid + 8 * p;
                    const int rr  = mlg >> 6;
                    const int wl  = mlg & 63;
                    g_t3h[(((size_t)n * Cc + co) * Hh + (h0 + rr)) * Ww + (w0 + wl)]
                        = __float2half(acc[mt][nt][2 * p + j]);
                }
            }
        }
    }
}

// ---------------- epilogue: CTA per (n, co, 32-h chunk); sliding window ----------------
__global__ __launch_bounds__(256)
void epilogue_kernel(const float* __restrict__ x,
                     const float* __restrict__ w7,
                     float* __restrict__ out)
{
    __shared__ float sx[34][136];        // rows h0-1..h0+32; p = col+4; pads zero
    const int blk = blockIdx.x;
    const int h0  = (blk & 3) * 32;
    const int co  = (blk >> 2) & (Cc - 1);
    const int n   = blk >> 8;
    const int tid = threadIdx.x;
    const int wid = tid >> 5;
    const int lane = tid & 31;

    const float* xc = x + ((size_t)n * Cc + co) * Hh * Ww;

    // stage: 34 rows x 34 float4
    for (int i = tid; i < 34 * 34; i += 256) {
        int s = i / 34, q = i - s * 34;
        int hh  = h0 - 1 + s;
        int col = 4 * q - 4;
        float4 v = make_float4(0.f, 0.f, 0.f, 0.f);
        if ((unsigned)hh < (unsigned)Hh && (unsigned)col < (unsigned)Ww)
            v = *(const float4*)(xc + (size_t)hh * Ww + col);
        *(float4*)(&sx[s][4 * q]) = v;
    }
    __syncthreads();

    float wk[9];
    #pragma unroll
    for (int q = 0; q < 9; q++) wk[q] = __ldg(w7 + co * 9 + q);

    const int w   = lane * 4;
    const int hl0 = wid * 4;

    // sliding 3-row register ring; rb[s] holds absolute local row (hl0-1+a) where a%3==s
    float rb[3][12];
    #define LOAD_ROW(slot, rowidx) do {                                            \
        const float* _rp = &sx[(rowidx)][w];                                       \
        _Pragma("unroll")                                                          \
        for (int _q = 0; _q < 3; _q++) {                                           \
            float4 _v = *(const float4*)(_rp + 4 * _q);                            \
            rb[slot][4 * _q + 0] = _v.x;                                           \
            rb[slot][4 * _q + 1] = _v.y;                                           \
            rb[slot][4 * _q + 2] = _v.z;                                           \
            rb[slot][4 * _q + 3] = _v.w;                                           \
        }                                                                          \
    } while (0)

    LOAD_ROW(0, hl0 + 0);   // row h-1 for r=0
    LOAD_ROW(1, hl0 + 1);   // row h
    LOAD_ROW(2, hl0 + 2);   // row h+1

    #pragma unroll
    for (int r = 0; r < 4; r++) {
        if (r > 0) LOAD_ROW((r + 2) % 3, hl0 + r + 2);   // new bottom row

        const int hl = hl0 + r;
        const int h  = h0 + hl;
        // i-th window row (i=0,1,2) is rb[(r+i)%3]
        const float* w0r = rb[(r + 0) % 3];
        const float* w1r = rb[(r + 1) % 3];
        const float* w2r = rb[(r + 2) % 3];
        const float* wrow[3] = {w0r, w1r, w2r};

        const size_t oidx = (((size_t)n * Cc + co) * Hh + h) * Ww + w;
        const __half2* t3p = (const __half2*)(g_t3h + oidx);
        float2 t3a = __half22float2(t3p[0]);
        float2 t3b = __half22float2(t3p[1]);
        float t3f[4] = {t3a.x, t3a.y, t3b.x, t3b.y};

        float res[4];
        #pragma unroll
        for (int k = 0; k < 4; k++) {
            float t7 = 0.f;
            if (k > 0 || w != 0) {
                #pragma unroll
                for (int i = 0; i < 3; i++) {
                    const float t1 = w1r[k + 2 * i + 2];
                    #pragma unroll
                    for (int jj = 0; jj < 3; jj++) {
                        const float t5 = wrow[i][k + 2 * jj + 1];
                        t7 = fmaf(wk[3 * jj + i], fmaxf(t1, t5), t7);
                    }
                }
            } else {
                // w == 0: roll wraps -> wr = 127; t5 = sx[hl+i][129+2jj] (col 129 OOB -> pad 0)
                #pragma unroll
                for (int i = 0; i < 3; i++) {
                    const float t1 = w1r[2 * i + 2];
                    #pragma unroll
                    for (int jj = 0; jj < 3; jj++) {
                        const float t5 = sx[hl + i][129 + 2 * jj];
                        t7 = fmaf(wk[3 * jj + i], fmaxf(t1, t5), t7);
                    }
                }
            }
            res[k] = t7;
        }
        float4 o;
        o.x = res[0] * t3f[0];
        o.y = res[1] * t3f[1];
        o.z = res[2] * t3f[2];
        o.w = res[3] * t3f[3];
        *(float4*)(out + oidx) = o;
    }
    #undef LOAD_ROW
}

extern "C" void kernel_launch(void* const* d_in, const int* in_sizes, int n_in,
                              void* d_out, int out_size)
{
    const float* x  = (const float*)d_in[0];
    const float* w3 = (const float*)d_in[1];
    const float* w7 = (const float*)d_in[2];
    float* out = (float*)d_out;

    prep_kernel<<<Nn * Hh + 20, 256>>>(x, w3);

    cudaFuncSetAttribute(gemm_kernel,
                         cudaFuncAttributeMaxDynamicSharedMemorySize, SMEM_BYTES);
    gemm_kernel<<<Nn * 64 * 2, NTHR, SMEM_BYTES>>>();

    epilogue_kernel<<<Nn * Cc * 4, 256>>>(x, w7, out);
}

// round 17
// speedup vs baseline: 1.2864x; 1.0850x over previous
#include <cuda_runtime.h>
#include <cuda_fp16.h>
#include <cstdint>

#define Nn 16
#define Cc 64
#define Hh 128
#define Ww 128

#define SMEM_BYTES (144 * 128)
#define NTHR 256

#define SWZ(o) ((uint32_t)(o) ^ ((((uint32_t)(o)) >> 3) & 0x70))

__device__ __align__(16) uint4 g_Bfrag[5 * 4 * 8 * 32];
__device__ __align__(16) __half g_t3h[(size_t)Nn * Cc * Hh * Ww];
__device__ __align__(16) __half g_xh[(size_t)Nn * Hh * 136 * 64];

// ---------------- helpers ----------------
__device__ __forceinline__ uint32_t smem_u32(const void* p) {
    uint32_t a;
    asm("{ .reg .u64 t; cvta.to.shared.u64 t, %1; cvt.u32.u64 %0, t; }" : "=r"(a) : "l"(p));
    return a;
}
__device__ __forceinline__ void ldx4(uint32_t* r, uint32_t addr) {
    asm volatile("ldmatrix.sync.aligned.m8n8.x4.shared.b16 {%0,%1,%2,%3}, [%4];"
                 : "=r"(r[0]), "=r"(r[1]), "=r"(r[2]), "=r"(r[3]) : "r"(addr));
}
__device__ __forceinline__ void mma_f16(float* d, const uint32_t* a, uint32_t b0, uint32_t b1) {
    asm volatile(
        "mma.sync.aligned.m16n8k16.row.col.f32.f16.f16.f32 "
        "{%0,%1,%2,%3}, {%4,%5,%6,%7}, {%8,%9}, {%0,%1,%2,%3};"
        : "+f"(d[0]), "+f"(d[1]), "+f"(d[2]), "+f"(d[3])
        : "r"(a[0]), "r"(a[1]), "r"(a[2]), "r"(a[3]), "r"(b0), "r"(b1));
}
__device__ __forceinline__ uint32_t pack_h2(float lo, float hi_) {
    __half2 p;
    p.x = __float2half(lo);
    p.y = __float2half(hi_);
    return *(uint32_t*)&p;
}

// ---------------- prep: xcvt (blocks 0..2047, fp16 tile) + convert_w (2048..2067) ----------------
__global__ __launch_bounds__(256)
void prep_kernel(const float* __restrict__ x, const float* __restrict__ w3)
{
    if (blockIdx.x >= Nn * Hh) {
        int idx = (blockIdx.x - Nn * Hh) * 256 + threadIdx.x;
        if (idx >= 5 * 4 * 8 * 32) return;
        int lane = idx & 31;
        int nt8  = (idx >> 5) & 7;
        int kc   = (idx >> 8) & 3;
        int tap  = idx >> 10;

        int co  = nt8 * 8 + (lane >> 2);
        int ci0 = kc * 16 + (lane & 3) * 2;

        float v[4], hi[4], lo[4];
        #pragma unroll
        for (int q = 0; q < 4; q++) {
            int ci = ci0 + (q & 1) + (q >> 1) * 8;
            v[q] = w3[((size_t)co * Cc + ci) * 5 + tap];
            __half hb = __float2half(v[q]);
            hi[q] = __half2float(hb);
            lo[q] = v[q] - hi[q];
        }
        uint4 frag;
        frag.x = pack_h2(hi[0], hi[1]);
        frag.y = pack_h2(hi[2], hi[3]);
        frag.z = pack_h2(lo[0], lo[1]);
        frag.w = pack_h2(lo[2], lo[3]);
        g_Bfrag[idx] = frag;
        return;
    }

    // fp16 tile: 64 x 132 halves (row 264B, 8B-aligned) = 16.9 KB -> ~13 CTAs/SM
    __shared__ __half tileh[64][132];
    const int nh  = blockIdx.x;
    const int h   = nh & (Hh - 1);
    const int n   = nh >> 7;
    const int tid = threadIdx.x;

    for (int i = tid; i < 64 * 32; i += 256) {
        int f = i & 31, c = i >> 5;
        float4 v = *(const float4*)(x + (((size_t)n * Cc + c) * Hh + h) * Ww + 4 * f);
        uint2 pk;
        pk.x = pack_h2(v.x, v.y);
        pk.y = pack_h2(v.z, v.w);
        *(uint2*)&tileh[c][4 * f] = pk;
    }
    __syncthreads();

    uint32_t* gh = (uint32_t*)g_xh;
    const size_t rowbase = (size_t)nh * 136;
    for (int i = tid; i < 136 * 32; i += 256) {
        int ci2 = i & 31, wp = i >> 5;
        int w = wp - 2;
        uint32_t val = 0;
        if ((unsigned)w < (unsigned)Ww) {
            uint32_t lo = __half_as_ushort(tileh[2 * ci2][w]);
            uint32_t hi = __half_as_ushort(tileh[2 * ci2 + 1][w]);
            val = lo | (hi << 16);
        }
        uint32_t boff = ((uint32_t)(ci2 * 4)) ^ ((uint32_t)(wp & 7) << 4);
        gh[(rowbase + wp) * 32 + (boff >> 2)] = val;
    }
}

// ---------------- main kernel: pure GEMM -> g_t3h (smem-staged stores) ----------------
__global__ __launch_bounds__(NTHR, 2)
void gemm_kernel()
{
    extern __shared__ char smem[];
    const uint32_t sbase = smem_u32(smem);

    const int tid  = threadIdx.x;
    const int wid  = tid >> 5;
    const int lane = tid & 31;
    const int wblk = blockIdx.x & 1;
    const int h0   = ((blockIdx.x >> 1) & 63) * 2;
    const int n    = blockIdx.x >> 7;
    const int w0   = wblk * 64;

    {
        const uint4* src0 = (const uint4*)g_xh + ((size_t)(n * Hh + h0)     * 136 + w0) * 8;
        const uint4* src1 = (const uint4*)g_xh + ((size_t)(n * Hh + h0 + 1) * 136 + w0) * 8;
        uint4* d = (uint4*)smem;
        for (int i = tid; i < 1088; i += NTHR) {
            int b = (i >= 544);
            int j = i - 544 * b;
            uint4 v = b ? src1[j] : src0[j];
            d[b * 576 + j] = v;
        }
    }
    __syncthreads();

    const int warp_m = wid & 3;
    const int warp_n = wid >> 2;
    const int arow_base = (warp_m < 2) ? (32 * warp_m) : (72 + 32 * (warp_m - 2));
    const int mlg_base  = 32 * warp_m;

    const int gid = lane >> 2;
    const int tig = lane & 3;
    const int arow   = (lane & 7) + ((lane >> 3) & 1) * 8;
    const int acol16 = (lane >> 4) * 16;

    const uint4* bt = g_Bfrag + (size_t)(warp_n * 4) * 32 + lane;

    float acc[2][4][4];
    #pragma unroll
    for (int mt = 0; mt < 2; mt++)
        #pragma unroll
        for (int nt = 0; nt < 4; nt++)
            #pragma unroll
            for (int r = 0; r < 4; r++) acc[mt][nt][r] = 0.f;

    uint32_t aH[2][2][4];
    uint4 bf[2][4];

    #define LOAD_STAGE(s, buf) do {                                                \
        const int _tap = (s) >> 2, _kc = (s) & 3;                                  \
        _Pragma("unroll")                                                          \
        for (int mt = 0; mt < 2; mt++) {                                           \
            uint32_t rel = (uint32_t)((arow_base + 16 * mt + _tap + arow) * 128    \
                                      + _kc * 32 + acol16);                        \
            ldx4(aH[buf][mt], sbase + SWZ(rel));                                   \
        }                                                                          \
        _Pragma("unroll")                                                          \
        for (int nt = 0; nt < 4; nt++)                                             \
            bf[buf][nt] = __ldg(bt + (size_t)(_tap * 4 + _kc) * 256 + nt * 32);    \
    } while (0)

    #define MMA_STAGE(buf) do {                                                    \
        _Pragma("unroll")                                                          \
        for (int mt = 0; mt < 2; mt++)                                             \
            _Pragma("unroll")                                                      \
            for (int nt = 0; nt < 4; nt++)                                         \
                mma_f16(acc[mt][nt], aH[buf][mt], bf[buf][nt].x, bf[buf][nt].y);   \
        _Pragma("unroll")                                                          \
        for (int mt = 0; mt < 2; mt++)                                             \
            _Pragma("unroll")                                                      \
            for (int nt = 0; nt < 4; nt++)                                         \
                mma_f16(acc[mt][nt], aH[buf][mt], bf[buf][nt].z, bf[buf][nt].w);   \
    } while (0)

    LOAD_STAGE(0, 0);
    #pragma unroll
    for (int s = 0; s < 20; s++) {
        if (s + 1 < 20) {
            if ((s & 1) == 0) LOAD_STAGE(s + 1, 1);
            else              LOAD_STAGE(s + 1, 0);
        }
        if ((s & 1) == 0) MMA_STAGE(0);
        else              MMA_STAGE(1);
    }
    #undef LOAD_STAGE
    #undef MMA_STAGE

    // ---- stage t3 through smem (reuse Xp region), then coalesced store ----
    __syncthreads();                         // all Xp reads complete before overwrite
    {
        __half* st3 = (__half*)smem;         // [co][mlg] rows of 136 halves (272B)
        #pragma unroll
        for (int nt = 0; nt < 4; nt++)
            #pragma unroll
            for (int j = 0; j < 2; j++) {
                const int co = 32 * warp_n + 8 * nt + 2 * tig + j;
                #pragma unroll
                for (int mt = 0; mt < 2; mt++)
                    #pragma unroll
                    for (int p = 0; p < 2; p++) {
                        const int mlg = mlg_base + 16 * mt + gid + 8 * p;
                        st3[co * 136 + mlg] = __float2half(acc[mt][nt][2 * p + j]);
                    }
            }
    }
    __syncthreads();
    {
        // 1024 x 16B chunks: chunk t -> co = t>>4, rr = (t>>3)&1, q = t&7
        for (int t = tid; t < 1024; t += NTHR) {
            int co = t >> 4, rr = (t >> 3) & 1, q = t & 7;
            uint4 v = *(const uint4*)(smem + co * 272 + rr * 128 + q * 16);
            *(uint4*)(g_t3h + ((((size_t)n * Cc + co) * Hh) + (h0 + rr)) * Ww + w0 + q * 8) = v;
        }
    }
}

// ---------------- epilogue: CTA per (n, co, 32-h chunk); sliding window ----------------
__global__ __launch_bounds__(256)
void epilogue_kernel(const float* __restrict__ x,
                     const float* __restrict__ w7,
                     float* __restrict__ out)
{
    __shared__ float sx[34][136];        // rows h0-1..h0+32; p = col+4; pads zero
    const int blk = blockIdx.x;
    const int h0  = (blk & 3) * 32;
    const int co  = (blk >> 2) & (Cc - 1);
    const int n   = blk >> 8;
    const int tid = threadIdx.x;
    const int wid = tid >> 5;
    const int lane = tid & 31;

    const float* xc = x + ((size_t)n * Cc + co) * Hh * Ww;

    for (int i = tid; i < 34 * 34; i += 256) {
        int s = i / 34, q = i - s * 34;
        int hh  = h0 - 1 + s;
        int col = 4 * q - 4;
        float4 v = make_float4(0.f, 0.f, 0.f, 0.f);
        if ((unsigned)hh < (unsigned)Hh && (unsigned)col < (unsigned)Ww)
            v = *(const float4*)(xc + (size_t)hh * Ww + col);
        *(float4*)(&sx[s][4 * q]) = v;
    }
    __syncthreads();

    float wk[9];
    #pragma unroll
    for (int q = 0; q < 9; q++) wk[q] = __ldg(w7 + co * 9 + q);

    const int w   = lane * 4;
    const int hl0 = wid * 4;
    const bool w0lane = (w == 0);

    float rb[3][12];
    #define LOAD_ROW(slot, rowidx) do {                                            \
        const float* _rp = &sx[(rowidx)][w];                                       \
        _Pragma("unroll")                                                          \
        for (int _q = 0; _q < 3; _q++) {                                           \
            float4 _v = *(const float4*)(_rp + 4 * _q);                            \
            rb[slot][4 * _q + 0] = _v.x;                                           \
            rb[slot][4 * _q + 1] = _v.y;                                           \
            rb[slot][4 * _q + 2] = _v.z;                                           \
            rb[slot][4 * _q + 3] = _v.w;                                           \
        }                                                                          \
    } while (0)

    LOAD_ROW(0, hl0 + 0);
    LOAD_ROW(1, hl0 + 1);
    LOAD_ROW(2, hl0 + 2);

    #pragma unroll
    for (int r = 0; r < 4; r++) {
        if (r > 0) LOAD_ROW((r + 2) % 3, hl0 + r + 2);

        const int hl = hl0 + r;
        const int h  = h0 + hl;
        const float* wrow[3] = {rb[(r + 0) % 3], rb[(r + 1) % 3], rb[(r + 2) % 3]};
        const float* w1r = wrow[1];

        // wrap values (w==0, k==0 case): broadcast loads, uniform per warp
        float wrap[3][3];
        #pragma unroll
        for (int i = 0; i < 3; i++)
            #pragma unroll
            for (int jj = 0; jj < 3; jj++)
                wrap[i][jj] = sx[hl + i][129 + 2 * jj];

        const size_t oidx = (((size_t)n * Cc + co) * Hh + h) * Ww + w;
        const __half2* t3p = (const __half2*)(g_t3h + oidx);
        float2 t3a = __half22float2(t3p[0]);
        float2 t3b = __half22float2(t3p[1]);
        float t3f[4] = {t3a.x, t3a.y, t3b.x, t3b.y};

        float res[4];
        #pragma unroll
        for (int k = 0; k < 4; k++) {
            float t7 = 0.f;
            #pragma unroll
            for (int i = 0; i < 3; i++) {
                const float t1 = w1r[k + 2 * i + 2];
                #pragma unroll
                for (int jj = 0; jj < 3; jj++) {
                    float t5 = wrow[i][k + 2 * jj + 1];
                    if (k == 0) t5 = w0lane ? wrap[i][jj] : t5;   // SEL, no divergence
                    t7 = fmaf(wk[3 * jj + i], fmaxf(t1, t5), t7);
                }
            }
            res[k] = t7;
        }
        float4 o;
        o.x = res[0] * t3f[0];
        o.y = res[1] * t3f[1];
        o.z = res[2] * t3f[2];
        o.w = res[3] * t3f[3];
        *(float4*)(out + oidx) = o;
    }
    #undef LOAD_ROW
}

extern "C" void kernel_launch(void* const* d_in, const int* in_sizes, int n_in,
                              void* d_out, int out_size)
{
    const float* x  = (const float*)d_in[0];
    const float* w3 = (const float*)d_in[1];
    const float* w7 = (const float*)d_in[2];
    float* out = (float*)d_out;

    prep_kernel<<<Nn * Hh + 20, 256>>>(x, w3);

    cudaFuncSetAttribute(gemm_kernel,
                         cudaFuncAttributeMaxDynamicSharedMemorySize, SMEM_BYTES);
    gemm_kernel<<<Nn * 64 * 2, NTHR, SMEM_BYTES>>>();

    epilogue_kernel<<<Nn * Cc * 4, 256>>>(x, w7, out);
}